// round 5
// baseline (speedup 1.0000x reference)
#include <cuda_runtime.h>
#include <cstdint>

#define B_ 64
#define T_ 96
#define NV 4
#define NK_ 12
#define NF_ 17
#define HW_ 400
#define SIGLEN_ 306
#define KTOT_ 122400        // HW_*SIGLEN_
#define NCHUNK_ 255
#define KC_ 480             // NCHUNK_*KC_ == KTOT_

__device__ float g_sig [(size_t)B_ * HW_ * SIGLEN_];    // [b][p][s]  ~31 MB
__device__ float g_part[(size_t)NCHUNK_ * 64 * 32];

// ---- f32x2 packed-FMA helpers (two independent fp32 FMAs per instruction,
//      bitwise identical to scalar fmaf) ----
__device__ __forceinline__ unsigned long long pack2(float lo, float hi) {
    unsigned long long r;
    asm("mov.b64 %0, {%1, %2};" : "=l"(r) : "f"(lo), "f"(hi));
    return r;
}
__device__ __forceinline__ void ffma2(unsigned long long& d,
                                      unsigned long long a,
                                      unsigned long long b) {
    asm("fma.rn.f32x2 %0, %1, %2, %0;" : "+l"(d) : "l"(a), "l"(b));
}
__device__ __forceinline__ float2 unpack2(unsigned long long v) {
    float lo, hi;
    asm("mov.b64 {%0, %1}, %2;" : "=f"(lo), "=f"(hi) : "l"(v));
    return make_float2(lo, hi);
}

// ---------------------------------------------------------------------------
// Fused conv3x3(4->12) + feature assembly + path signature.
// Grid (4, 64): block = (5-row strip of 100 px, batch). 400 threads.
// Single __syncthreads per t: xs AND feat double-buffered so the only
// ordering needed is conv(t)-writes-feat -> bar -> sig(t)-reads-feat; the
// next iteration's xs stage / conv touch the other buffers.
//   lvl1_j  = p95_j - p0_j
//   lvl2_ij = 0.5*sum_t (p_t+p_{t-1})_i (p_t-p_{t-1})_j - p0_i*lvl1_j
// ---------------------------------------------------------------------------
__global__ __launch_bounds__(400, 1)
void fused_conv_sig_kernel(const float* __restrict__ x,
                           const float* __restrict__ cw,
                           const float* __restrict__ cb)
{
    __shared__ __align__(16) float xs[2][616];         // double-buffered halo (4v x 7 x 22)
    __shared__ __align__(16) float ws2[12 * 48];       // weights [k][v][12pad]
    __shared__ float wb[12];
    __shared__ __align__(16) float feat[2][17 * 101];  // double-buffered feature tile
    __shared__ float p0s[17 * 101];                    // t=0 snapshot

    const int cx = blockIdx.x;
    const int b  = blockIdx.y;
    const int tid = threadIdx.x;
    const int pbase = cx * 100;

    // init: zero both xs buffers (halo guards stay 0), repack weights
    for (int i = tid; i < 2 * 616; i += 400) ((float*)xs)[i] = 0.f;
    for (int i = tid; i < 432; i += 400) {
        const int k = i / 36, r = i % 36, v = r / 9, tap = r % 9;
        ws2[k * 48 + v * 12 + tap] = cw[i];
    }
    if (tid < 12) wb[tid] = cb[tid];

    // hoisted x-staging indices (2 legs)
    const float* xg = x + (size_t)b * T_ * NV * HW_;
    int gofA = -1, sofA = 0, gofB = -1, sofB = 0;
    {
        const int i = tid;
        const int v = i / 154, r = i % 154, row = r / 22, col = r % 22;
        const int gr = cx * 5 - 1 + row;
        if (gr >= 0 && gr < 20 && col >= 1 && col <= 20) {
            gofA = v * HW_ + gr * 20 + (col - 1); sofA = i;
        }
    }
    if (tid + 400 < 616) {
        const int i = tid + 400;
        const int v = i / 154, r = i % 154, row = r / 22, col = r % 22;
        const int gr = cx * 5 - 1 + row;
        if (gr >= 0 && gr < 20 && col >= 1 && col <= 20) {
            gofB = v * HW_ + gr * 20 + (col - 1); sofB = i;
        }
    }

    // conv role: pixel px, channel group kq (3 channels)
    const int px = tid % 100, kq = tid / 100;
    const int row0 = px / 20, col0 = px % 20;
    const int xoff = row0 * 22 + col0;

    // sig role: pixel pp, quadrant q
    const int pp = tid >> 2, q = tid & 3;
    const int i0 = (q >> 1) * 8, j0 = (q & 1) * 8;

    // stage x_0 into xs[0], prefetch x_1
    float rvA = 0.f, rvB = 0.f;
    if (gofA >= 0) rvA = xg[gofA];
    if (gofB >= 0) rvB = xg[gofB];
    if (gofA >= 0) xs[0][sofA] = rvA;
    if (gofB >= 0) xs[0][sofB] = rvB;
    {
        const float* xn = xg + (size_t)NV * HW_;
        if (gofA >= 0) rvA = xn[gofA];
        if (gofB >= 0) rvB = xn[gofB];
    }
    __syncthreads();   // ws2/wb + xs[0] ready

    const float bi0 = wb[kq * 3], bi1 = wb[kq * 3 + 1], bi2 = wb[kq * 3 + 2];

    // conv body as a lambda-free macro-ish block, used twice
#define CONV_STEP(XB, FT, TVAL)                                            \
    {                                                                      \
        const float* xrow = (XB) + xoff;                                   \
        float a0 = bi0, a1 = bi1, a2 = bi2;                                \
        _Pragma("unroll")                                                  \
        for (int v = 0; v < 4; v++) {                                      \
            float xv[9];                                                   \
            _Pragma("unroll")                                              \
            for (int dy = 0; dy < 3; dy++)                                 \
                _Pragma("unroll")                                          \
                for (int dx = 0; dx < 3; dx++)                             \
                    xv[dy * 3 + dx] = xrow[v * 154 + dy * 22 + dx];        \
            _Pragma("unroll")                                              \
            for (int c = 0; c < 3; c++) {                                  \
                const float4* wp = (const float4*)(ws2 + (kq * 3 + c) * 48 + v * 12); \
                const float4 w0 = wp[0];                                   \
                const float4 w1 = wp[1];                                   \
                const float w8 = ws2[(kq * 3 + c) * 48 + v * 12 + 8];      \
                float s = xv[0] * w0.x;                                    \
                s = fmaf(xv[1], w0.y, s);                                  \
                s = fmaf(xv[2], w0.z, s);                                  \
                s = fmaf(xv[3], w0.w, s);                                  \
                s = fmaf(xv[4], w1.x, s);                                  \
                s = fmaf(xv[5], w1.y, s);                                  \
                s = fmaf(xv[6], w1.z, s);                                  \
                s = fmaf(xv[7], w1.w, s);                                  \
                s = fmaf(xv[8], w8, s);                                    \
                if (c == 0) a0 += s; else if (c == 1) a1 += s; else a2 += s; \
            }                                                              \
        }                                                                  \
        (FT)[(kq * 3 + 0) * 101 + px] = a0;                                \
        (FT)[(kq * 3 + 1) * 101 + px] = a1;                                \
        (FT)[(kq * 3 + 2) * 101 + px] = a2;                                \
        (FT)[(12 + kq) * 101 + px] = xrow[kq * 154 + 23];                  \
        if (kq == 0) (FT)[16 * 101 + px] = (TVAL);                         \
    }

    // conv(0) -> feat[0]; stage xs[1]=x1; prefetch x2
    CONV_STEP(xs[0], feat[0], 0.f)
    if (gofA >= 0) xs[1][sofA] = rvA;
    if (gofB >= 0) xs[1][sofB] = rvB;
    {
        const float* xn = xg + (size_t)2 * NV * HW_;
        if (gofA >= 0) rvA = xn[gofA];
        if (gofB >= 0) rvB = xn[gofB];
    }
    __syncthreads();   // feat[0] + xs[1] ready

    // sig init from feat[0]
    float pi[9], pj[9], d[9], acc1[9];
    unsigned long long acc2[9][4], d2[4];
#pragma unroll
    for (int a = 0; a < 9; a++) pi[a] = feat[0][(i0 + a) * 101 + pp];
#pragma unroll
    for (int c = 0; c < 9; c++) pj[c] = feat[0][(j0 + c) * 101 + pp];
#pragma unroll
    for (int a = 0; a < 9; a++) {
        acc1[a] = 0.f;
#pragma unroll
        for (int cp = 0; cp < 4; cp++) acc2[a][cp] = 0ull;
    }
    for (int i = tid; i < 17 * 101; i += 400) p0s[i] = feat[0][i];

    for (int k = 1; k < T_; k++) {
        const int buf = k & 1;
        float* ft = feat[buf];
        const float* xb = xs[buf];

        // stage x_{k+1} into the other xs buffer; prefetch x_{k+2} (clamped)
        if (gofA >= 0) xs[buf ^ 1][sofA] = rvA;
        if (gofB >= 0) xs[buf ^ 1][sofB] = rvB;
        {
            const int tn = (k + 2 < T_) ? (k + 2) : (T_ - 1);
            const float* xn = xg + (size_t)tn * NV * HW_;
            if (gofA >= 0) rvA = xn[gofA];
            if (gofB >= 0) rvB = xn[gofB];
        }

        // conv(k): xs[buf] (staged last iter, bar-protected) -> feat[buf]
        CONV_STEP(xb, ft, (float)k * (1.0f / 95.0f))

        __syncthreads();   // the ONLY bar per t

        // sig(k): packed-f32x2 rank-1 update
#pragma unroll
        for (int c = 0; c < 9; c++) {
            const float cv = ft[(j0 + c) * 101 + pp];
            d[c] = cv - pj[c];
            pj[c] = cv;
        }
        d2[0] = pack2(d[0], d[1]);
        d2[1] = pack2(d[2], d[3]);
        d2[2] = pack2(d[4], d[5]);
        d2[3] = pack2(d[6], d[7]);
#pragma unroll
        for (int a = 0; a < 9; a++) {
            const float cv = ft[(i0 + a) * 101 + pp];
            const float m = cv + pi[a];      // 0.5 deferred
            pi[a] = cv;
            const unsigned long long m2 = pack2(m, m);
            ffma2(acc2[a][0], m2, d2[0]);
            ffma2(acc2[a][1], m2, d2[1]);
            ffma2(acc2[a][2], m2, d2[2]);
            ffma2(acc2[a][3], m2, d2[3]);
            acc1[a] = fmaf(m, d[8], acc1[a]);
        }
    }
#undef CONV_STEP

    // epilogue
    float p0i[9], l1[9];
#pragma unroll
    for (int a = 0; a < 9; a++) p0i[a] = p0s[(i0 + a) * 101 + pp];
#pragma unroll
    for (int c = 0; c < 9; c++) l1[c] = pj[c] - p0s[(j0 + c) * 101 + pp];

    float* sg = g_sig + ((size_t)b * HW_ + pbase + pp) * SIGLEN_;
    if (q < 2) {
#pragma unroll
        for (int c = 0; c < 9; c++) sg[j0 + c] = l1[c];
    }
#pragma unroll
    for (int a = 0; a < 9; a++) {
#pragma unroll
        for (int cp = 0; cp < 4; cp++) {
            const float2 v = unpack2(acc2[a][cp]);
            sg[17 + (i0 + a) * 17 + (j0 + 2 * cp)]     = 0.5f * v.x - p0i[a] * l1[2 * cp];
            sg[17 + (i0 + a) * 17 + (j0 + 2 * cp + 1)] = 0.5f * v.y - p0i[a] * l1[2 * cp + 1];
        }
        sg[17 + (i0 + a) * 17 + (j0 + 8)] = 0.5f * acc1[a] - p0i[a] * l1[8];
    }
}

// ---------------------------------------------------------------------------
// Layer-1 GEMM partials over K=122400, 255 chunks of 480. Reg prefetch.
// ---------------------------------------------------------------------------
__global__ __launch_bounds__(256)
void mlp1_kernel(const float* __restrict__ w1)
{
    __shared__ __align__(16) float ss[32 * 66];
    __shared__ __align__(16) float wsm[32 * 32];

    const int cx = blockIdx.x, tid = threadIdx.x;
    const int oq = tid & 7, bq = tid >> 3;
    const int b0 = bq * 2, o0 = oq * 4;
    const int kb = cx * KC_;

    float ps[8], pw[4];
    {
        const int k0 = kb;
#pragma unroll
        for (int r = 0; r < 8; r++) {
            const int idx = tid + r * 256;
            ps[r] = g_sig[(size_t)(idx >> 5) * KTOT_ + k0 + (idx & 31)];
        }
#pragma unroll
        for (int r = 0; r < 4; r++) {
            const int idx = tid + r * 256;
            pw[r] = w1[(size_t)(k0 + (idx >> 5)) * 32 + (idx & 31)];
        }
    }

    float acc[2][4] = {};

    for (int tile = 0; tile < KC_ / 32; tile++) {
#pragma unroll
        for (int r = 0; r < 8; r++) {
            const int idx = tid + r * 256;
            ss[(idx & 31) * 66 + (idx >> 5)] = ps[r];
        }
#pragma unroll
        for (int r = 0; r < 4; r++) {
            const int idx = tid + r * 256;
            wsm[(idx >> 5) * 32 + (idx & 31)] = pw[r];
        }
        if (tile < KC_ / 32 - 1) {
            const int k0 = kb + (tile + 1) * 32;
#pragma unroll
            for (int r = 0; r < 8; r++) {
                const int idx = tid + r * 256;
                ps[r] = g_sig[(size_t)(idx >> 5) * KTOT_ + k0 + (idx & 31)];
            }
#pragma unroll
            for (int r = 0; r < 4; r++) {
                const int idx = tid + r * 256;
                pw[r] = w1[(size_t)(k0 + (idx >> 5)) * 32 + (idx & 31)];
            }
        }
        __syncthreads();
#pragma unroll
        for (int kk = 0; kk < 32; kk++) {
            const float2 sv = *(const float2*)&ss[kk * 66 + b0];
            const float4 wv = *(const float4*)&wsm[kk * 32 + o0];
            acc[0][0] = fmaf(sv.x, wv.x, acc[0][0]);
            acc[0][1] = fmaf(sv.x, wv.y, acc[0][1]);
            acc[0][2] = fmaf(sv.x, wv.z, acc[0][2]);
            acc[0][3] = fmaf(sv.x, wv.w, acc[0][3]);
            acc[1][0] = fmaf(sv.y, wv.x, acc[1][0]);
            acc[1][1] = fmaf(sv.y, wv.y, acc[1][1]);
            acc[1][2] = fmaf(sv.y, wv.z, acc[1][2]);
            acc[1][3] = fmaf(sv.y, wv.w, acc[1][3]);
        }
        __syncthreads();
    }
#pragma unroll
    for (int i = 0; i < 2; i++)
#pragma unroll
        for (int j = 0; j < 4; j++)
            g_part[((size_t)cx * 64 + b0 + i) * 32 + o0 + j] = acc[i][j];
}

// ---------------------------------------------------------------------------
// Reduce partials + bias/relu + layers 2..4.
// ---------------------------------------------------------------------------
__global__ __launch_bounds__(256)
void mlp_tail_kernel(const float* __restrict__ b1,
                     const float* __restrict__ w2, const float* __restrict__ b2,
                     const float* __restrict__ w3, const float* __restrict__ b3,
                     const float* __restrict__ w4, const float* __restrict__ b4,
                     float* __restrict__ out)
{
    __shared__ float red[8][33];
    const int b = blockIdx.x, tid = threadIdx.x;
    const int o = tid & 31, g = tid >> 5;

    float s = 0.f;
    for (int c = g; c < NCHUNK_; c += 8)
        s += g_part[((size_t)c * 64 + b) * 32 + o];
    red[g][o] = s;
    __syncthreads();

    if (tid < 32) {
        float s1 = b1[o];
#pragma unroll
        for (int gg = 0; gg < 8; gg++) s1 += red[gg][o];
        float h = fmaxf(s1, 0.f);

        float s2 = b2[o];
#pragma unroll
        for (int k = 0; k < 32; k++)
            s2 = fmaf(__shfl_sync(0xffffffffu, h, k), w2[k * 32 + o], s2);
        h = fmaxf(s2, 0.f);

        float s3 = b3[o];
#pragma unroll
        for (int k = 0; k < 32; k++)
            s3 = fmaf(__shfl_sync(0xffffffffu, h, k), w3[k * 32 + o], s3);
        h = fmaxf(s3, 0.f);

        float v = h * w4[o];
#pragma unroll
        for (int off = 16; off; off >>= 1) v += __shfl_xor_sync(0xffffffffu, v, off);
        if (o == 0) out[b] = v + b4[0];
    }
}

// ---------------------------------------------------------------------------
extern "C" void kernel_launch(void* const* d_in, const int* in_sizes, int n_in,
                              void* d_out, int out_size)
{
    const float* x  = (const float*)d_in[0];
    const float* cw = (const float*)d_in[1];
    const float* cb = (const float*)d_in[2];
    const float* w1 = (const float*)d_in[3];
    const float* b1 = (const float*)d_in[4];
    const float* w2 = (const float*)d_in[5];
    const float* b2 = (const float*)d_in[6];
    const float* w3 = (const float*)d_in[7];
    const float* b3 = (const float*)d_in[8];
    const float* w4 = (const float*)d_in[9];
    const float* b4 = (const float*)d_in[10];
    float* out = (float*)d_out;

    fused_conv_sig_kernel<<<dim3(4, B_), 400>>>(x, cw, cb);
    mlp1_kernel<<<NCHUNK_, 256>>>(w1);
    mlp_tail_kernel<<<B_, 256>>>(b1, w2, b2, w3, b3, w4, b4, out);
}

// round 6
// speedup vs baseline: 1.0472x; 1.0472x over previous
#include <cuda_runtime.h>
#include <cstdint>

#define B_ 64
#define T_ 96
#define NV 4
#define NK_ 12
#define NF_ 17
#define HW_ 400
#define SIGLEN_ 306
#define KTOT_ 122400        // HW_*SIGLEN_
#define NCHUNK_ 255
#define KC_ 480             // NCHUNK_*KC_ == KTOT_

__device__ float g_sig [(size_t)B_ * HW_ * SIGLEN_];    // [b][p][s]  ~31 MB
__device__ float g_part[(size_t)NCHUNK_ * 64 * 32];

// ---------------------------------------------------------------------------
// Fused conv3x3(4->12) + feature exchange (warp shuffles) + path signature.
// Grid (4, 64): block = (5-row strip of 100 px, batch). 400 threads.
// tid = 4*pp + q: the 4 threads of pixel pp are adjacent lanes of one warp.
//   conv: thread computes channels 3q..3q+2 (+ copy ch 12+q, + time) of its
//         OWN pixel -> 5 register values; feat never goes through smem.
//   exchange: 17 shuffles within the 4-lane group gather the pixel's full
//         feature vector into registers.
//   sig: quadrant (i0,j0) = ((q>>1)*8, (q&1)*8), 9x9 acc in registers.
// Two timesteps per phase (shared weight loads), 4-deep xs buffers,
// ONE __syncthreads per 2 timesteps.
//   lvl1_j  = p95_j - p0_j
//   lvl2_ij = 0.5*sum_t (p_t+p_{t-1})_i (p_t-p_{t-1})_j - p0_i*lvl1_j
// ---------------------------------------------------------------------------
__global__ __launch_bounds__(400, 1)
void fused_conv_sig_kernel(const float* __restrict__ x,
                           const float* __restrict__ cw,
                           const float* __restrict__ cb)
{
    __shared__ __align__(16) float xs[2][2][616];   // [parity][t-in-pair][4v x 7 x 22]
    __shared__ __align__(16) float ws2[12 * 48];    // weights [k][v][12pad]
    __shared__ float wb[12];
    __shared__ float p0s[17 * 100];                 // t=0 feature snapshot

    const int cx = blockIdx.x;          // 5-row strip
    const int b  = blockIdx.y;
    const int tid = threadIdx.x;
    const int pbase = cx * 100;

    // ---- init: zero all xs buffers (halo guards stay 0), repack weights ----
    for (int i = tid; i < 4 * 616; i += 400) (&xs[0][0][0])[i] = 0.f;
    for (int i = tid; i < 432; i += 400) {
        const int k = i / 36, r = i % 36, v = r / 9, tap = r % 9;
        ws2[k * 48 + v * 12 + tap] = cw[i];
    }
    if (tid < 12) wb[tid] = cb[tid];

    const int pp = tid >> 2, q = tid & 3;
    const int lane = tid & 31;
    const int base = lane & ~3;
    const unsigned mask4 = 0xFu << base;
    const int row0 = pp / 20, col0 = pp % 20;
    const int xoff = row0 * 22 + col0;
    const int k0ch = 3 * q;

    // x-staging offsets (leg A: i=tid, leg B: i=tid+400 when tid<216)
    const float* xg = x + (size_t)b * T_ * NV * HW_;
    int gofA = -1, sofA = 0, gofB = -1, sofB = 0;
    {
        const int i = tid;
        const int v = i / 154, r = i % 154, row = r / 22, col = r % 22;
        const int gr = cx * 5 - 1 + row;
        if (gr >= 0 && gr < 20 && col >= 1 && col <= 20) {
            gofA = v * HW_ + gr * 20 + (col - 1); sofA = i;
        }
    }
    if (tid < 216) {
        const int i = tid + 400;
        const int v = i / 154, r = i % 154, row = r / 22, col = r % 22;
        const int gr = cx * 5 - 1 + row;
        if (gr >= 0 && gr < 20 && col >= 1 && col <= 20) {
            gofB = v * HW_ + gr * 20 + (col - 1); sofB = i;
        }
    }

    __syncthreads();   // ws2/wb + zeroed xs visible

    const float bi0 = wb[k0ch], bi1 = wb[k0ch + 1], bi2 = wb[k0ch + 2];

    // prefetch pair 0 (t=0,1)
    float rvA0 = 0.f, rvA1 = 0.f, rvB0 = 0.f, rvB1 = 0.f;
    if (gofA >= 0) { rvA0 = xg[gofA]; rvA1 = xg[gofA + NV * HW_]; }
    if (gofB >= 0) { rvB0 = xg[gofB]; rvB1 = xg[gofB + NV * HW_]; }

    float pi[9], pj[9], acc[9][9];
#pragma unroll
    for (int a = 0; a < 9; a++)
#pragma unroll
        for (int c = 0; c < 9; c++) acc[a][c] = 0.f;

    // conv for one timestep buffer (weights already in w-registers per v/c)
    // done inline below to share weight loads between the two timesteps.

    for (int kp = 0; kp < T_ / 2; kp++) {
        const int par = kp & 1;
        float* xA = xs[par][0];
        float* xB = xs[par][1];

        // store staged pair
        if (gofA >= 0) { xA[sofA] = rvA0; xB[sofA] = rvA1; }
        if (gofB >= 0) { xA[sofB] = rvB0; xB[sofB] = rvB1; }
        // prefetch next pair (clamped)
        {
            const int t2 = (2 * kp + 2 < T_) ? 2 * kp + 2 : T_ - 2;
            const float* xn = xg + (size_t)t2 * NV * HW_;
            if (gofA >= 0) { rvA0 = xn[gofA]; rvA1 = xn[gofA + NV * HW_]; }
            if (gofB >= 0) { rvB0 = xn[gofB]; rvB1 = xn[gofB + NV * HW_]; }
        }
        __syncthreads();   // the ONLY bar per 2 timesteps

        // ---- conv for both timesteps, sharing weight loads ----
        float myfA[5], myfB[5];
        {
            float a0A = bi0, a1A = bi1, a2A = bi2;
            float a0B = bi0, a1B = bi1, a2B = bi2;
#pragma unroll
            for (int v = 0; v < 4; v++) {
                float xvA[9], xvB[9];
#pragma unroll
                for (int dy = 0; dy < 3; dy++)
#pragma unroll
                    for (int dx = 0; dx < 3; dx++) {
                        const int o = xoff + v * 154 + dy * 22 + dx;
                        xvA[dy * 3 + dx] = xA[o];
                        xvB[dy * 3 + dx] = xB[o];
                    }
#pragma unroll
                for (int c = 0; c < 3; c++) {
                    const float4* wp = (const float4*)(ws2 + (k0ch + c) * 48 + v * 12);
                    const float4 w0 = wp[0];
                    const float4 w1 = wp[1];
                    const float w8 = ws2[(k0ch + c) * 48 + v * 12 + 8];
                    float sA = xvA[0] * w0.x;
                    sA = fmaf(xvA[1], w0.y, sA);
                    sA = fmaf(xvA[2], w0.z, sA);
                    sA = fmaf(xvA[3], w0.w, sA);
                    sA = fmaf(xvA[4], w1.x, sA);
                    sA = fmaf(xvA[5], w1.y, sA);
                    sA = fmaf(xvA[6], w1.z, sA);
                    sA = fmaf(xvA[7], w1.w, sA);
                    sA = fmaf(xvA[8], w8, sA);
                    float sB = xvB[0] * w0.x;
                    sB = fmaf(xvB[1], w0.y, sB);
                    sB = fmaf(xvB[2], w0.z, sB);
                    sB = fmaf(xvB[3], w0.w, sB);
                    sB = fmaf(xvB[4], w1.x, sB);
                    sB = fmaf(xvB[5], w1.y, sB);
                    sB = fmaf(xvB[6], w1.z, sB);
                    sB = fmaf(xvB[7], w1.w, sB);
                    sB = fmaf(xvB[8], w8, sB);
                    if (c == 0) { a0A += sA; a0B += sB; }
                    else if (c == 1) { a1A += sA; a1B += sB; }
                    else { a2A += sA; a2B += sB; }
                }
            }
            myfA[0] = a0A; myfA[1] = a1A; myfA[2] = a2A;
            myfB[0] = a0B; myfB[1] = a1B; myfB[2] = a2B;
            myfA[3] = xA[q * 154 + xoff + 23];   // copy channel 12+q
            myfB[3] = xB[q * 154 + xoff + 23];
            myfA[4] = (float)(2 * kp) * (1.0f / 95.0f);       // time channel
            myfB[4] = (float)(2 * kp + 1) * (1.0f / 95.0f);
        }

        // ---- exchange + signature, timestep A then B ----
#pragma unroll
        for (int s = 0; s < 2; s++) {
            const float* mf = s ? myfB : myfA;
            float cur[17];
#pragma unroll
            for (int f = 0; f < 12; f++)
                cur[f] = __shfl_sync(mask4, mf[f % 3], base + f / 3, 32);
#pragma unroll
            for (int v = 0; v < 4; v++)
                cur[12 + v] = __shfl_sync(mask4, mf[3], base + v, 32);
            cur[16] = __shfl_sync(mask4, mf[4], base, 32);

            // constant-index row/col selects (keeps cur in registers)
            float ci[9], cj[9];
#pragma unroll
            for (int a = 0; a < 9; a++) ci[a] = (q & 2) ? cur[8 + a] : cur[a];
#pragma unroll
            for (int c = 0; c < 9; c++) cj[c] = (q & 1) ? cur[8 + c] : cur[c];

            if (kp == 0 && s == 0) {
                // t = 0: init prev state, snapshot p0 to smem
#pragma unroll
                for (int a = 0; a < 9; a++) pi[a] = ci[a];
#pragma unroll
                for (int c = 0; c < 9; c++) pj[c] = cj[c];
#pragma unroll
                for (int c = 0; c < 3; c++) p0s[(k0ch + c) * 100 + pp] = mf[c];
                p0s[(12 + q) * 100 + pp] = mf[3];
                if (q == 0) p0s[16 * 100 + pp] = mf[4];
            } else {
                float d[9];
#pragma unroll
                for (int c = 0; c < 9; c++) {
                    d[c] = cj[c] - pj[c];
                    pj[c] = cj[c];
                }
#pragma unroll
                for (int a = 0; a < 9; a++) {
                    const float m = ci[a] + pi[a];   // 0.5 deferred
                    pi[a] = ci[a];
#pragma unroll
                    for (int c = 0; c < 9; c++)
                        acc[a][c] = fmaf(m, d[c], acc[a][c]);
                }
            }
        }
    }

    __syncthreads();   // p0s complete (written at t=0, read now)

    const int i0 = (q >> 1) * 8, j0 = (q & 1) * 8;
    float p0i[9], l1[9];
#pragma unroll
    for (int a = 0; a < 9; a++) p0i[a] = p0s[(i0 + a) * 100 + pp];
#pragma unroll
    for (int c = 0; c < 9; c++) l1[c] = pj[c] - p0s[(j0 + c) * 100 + pp];

    float* sg = g_sig + ((size_t)b * HW_ + pbase + pp) * SIGLEN_;
    if (q < 2) {
#pragma unroll
        for (int c = 0; c < 9; c++) sg[j0 + c] = l1[c];
    }
#pragma unroll
    for (int a = 0; a < 9; a++)
#pragma unroll
        for (int c = 0; c < 9; c++)
            sg[17 + (i0 + a) * 17 + (j0 + c)] = 0.5f * acc[a][c] - p0i[a] * l1[c];
}

// ---------------------------------------------------------------------------
// Layer-1 GEMM partials over K=122400, 255 chunks of 480. Reg prefetch.
// ---------------------------------------------------------------------------
__global__ __launch_bounds__(256)
void mlp1_kernel(const float* __restrict__ w1)
{
    __shared__ __align__(16) float ss[32 * 66];
    __shared__ __align__(16) float wsm[32 * 32];

    const int cx = blockIdx.x, tid = threadIdx.x;
    const int oq = tid & 7, bq = tid >> 3;
    const int b0 = bq * 2, o0 = oq * 4;
    const int kb = cx * KC_;

    float ps[8], pw[4];
    {
        const int k0 = kb;
#pragma unroll
        for (int r = 0; r < 8; r++) {
            const int idx = tid + r * 256;
            ps[r] = g_sig[(size_t)(idx >> 5) * KTOT_ + k0 + (idx & 31)];
        }
#pragma unroll
        for (int r = 0; r < 4; r++) {
            const int idx = tid + r * 256;
            pw[r] = w1[(size_t)(k0 + (idx >> 5)) * 32 + (idx & 31)];
        }
    }

    float acc[2][4] = {};

    for (int tile = 0; tile < KC_ / 32; tile++) {
#pragma unroll
        for (int r = 0; r < 8; r++) {
            const int idx = tid + r * 256;
            ss[(idx & 31) * 66 + (idx >> 5)] = ps[r];
        }
#pragma unroll
        for (int r = 0; r < 4; r++) {
            const int idx = tid + r * 256;
            wsm[(idx >> 5) * 32 + (idx & 31)] = pw[r];
        }
        if (tile < KC_ / 32 - 1) {
            const int k0 = kb + (tile + 1) * 32;
#pragma unroll
            for (int r = 0; r < 8; r++) {
                const int idx = tid + r * 256;
                ps[r] = g_sig[(size_t)(idx >> 5) * KTOT_ + k0 + (idx & 31)];
            }
#pragma unroll
            for (int r = 0; r < 4; r++) {
                const int idx = tid + r * 256;
                pw[r] = w1[(size_t)(k0 + (idx >> 5)) * 32 + (idx & 31)];
            }
        }
        __syncthreads();
#pragma unroll
        for (int kk = 0; kk < 32; kk++) {
            const float2 sv = *(const float2*)&ss[kk * 66 + b0];
            const float4 wv = *(const float4*)&wsm[kk * 32 + o0];
            acc[0][0] = fmaf(sv.x, wv.x, acc[0][0]);
            acc[0][1] = fmaf(sv.x, wv.y, acc[0][1]);
            acc[0][2] = fmaf(sv.x, wv.z, acc[0][2]);
            acc[0][3] = fmaf(sv.x, wv.w, acc[0][3]);
            acc[1][0] = fmaf(sv.y, wv.x, acc[1][0]);
            acc[1][1] = fmaf(sv.y, wv.y, acc[1][1]);
            acc[1][2] = fmaf(sv.y, wv.z, acc[1][2]);
            acc[1][3] = fmaf(sv.y, wv.w, acc[1][3]);
        }
        __syncthreads();
    }
#pragma unroll
    for (int i = 0; i < 2; i++)
#pragma unroll
        for (int j = 0; j < 4; j++)
            g_part[((size_t)cx * 64 + b0 + i) * 32 + o0 + j] = acc[i][j];
}

// ---------------------------------------------------------------------------
// Reduce partials + bias/relu + layers 2..4.
// ---------------------------------------------------------------------------
__global__ __launch_bounds__(256)
void mlp_tail_kernel(const float* __restrict__ b1,
                     const float* __restrict__ w2, const float* __restrict__ b2,
                     const float* __restrict__ w3, const float* __restrict__ b3,
                     const float* __restrict__ w4, const float* __restrict__ b4,
                     float* __restrict__ out)
{
    __shared__ float red[8][33];
    const int b = blockIdx.x, tid = threadIdx.x;
    const int o = tid & 31, g = tid >> 5;

    float s = 0.f;
    for (int c = g; c < NCHUNK_; c += 8)
        s += g_part[((size_t)c * 64 + b) * 32 + o];
    red[g][o] = s;
    __syncthreads();

    if (tid < 32) {
        float s1 = b1[o];
#pragma unroll
        for (int gg = 0; gg < 8; gg++) s1 += red[gg][o];
        float h = fmaxf(s1, 0.f);

        float s2 = b2[o];
#pragma unroll
        for (int k = 0; k < 32; k++)
            s2 = fmaf(__shfl_sync(0xffffffffu, h, k), w2[k * 32 + o], s2);
        h = fmaxf(s2, 0.f);

        float s3 = b3[o];
#pragma unroll
        for (int k = 0; k < 32; k++)
            s3 = fmaf(__shfl_sync(0xffffffffu, h, k), w3[k * 32 + o], s3);
        h = fmaxf(s3, 0.f);

        float v = h * w4[o];
#pragma unroll
        for (int off = 16; off; off >>= 1) v += __shfl_xor_sync(0xffffffffu, v, off);
        if (o == 0) out[b] = v + b4[0];
    }
}

// ---------------------------------------------------------------------------
extern "C" void kernel_launch(void* const* d_in, const int* in_sizes, int n_in,
                              void* d_out, int out_size)
{
    const float* x  = (const float*)d_in[0];
    const float* cw = (const float*)d_in[1];
    const float* cb = (const float*)d_in[2];
    const float* w1 = (const float*)d_in[3];
    const float* b1 = (const float*)d_in[4];
    const float* w2 = (const float*)d_in[5];
    const float* b2 = (const float*)d_in[6];
    const float* w3 = (const float*)d_in[7];
    const float* b3 = (const float*)d_in[8];
    const float* w4 = (const float*)d_in[9];
    const float* b4 = (const float*)d_in[10];
    float* out = (float*)d_out;

    fused_conv_sig_kernel<<<dim3(4, B_), 400>>>(x, cw, cb);
    mlp1_kernel<<<NCHUNK_, 256>>>(w1);
    mlp_tail_kernel<<<B_, 256>>>(b1, w2, b2, w3, b3, w4, b4, out);
}